// round 7
// baseline (speedup 1.0000x reference)
#include <cuda_runtime.h>

// GRU_39170101739852: B=4096, T=512, H=64 GRU + Linear(H->1), fp32.
// R7: 64-thread autonomous groups (thread = unit, full k) with per-group
// named barriers -> no CTA-wide sync, no reduction shuffles in the loop.
// h_t streamed to __device__ scratch; trailing Linear done by a 2nd kernel.

#define TT 512
#define HH 64
#define MB 32          // batches per CTA (4 groups x 8)
#define NTHREADS 256
#define NB 8           // batches per group
#define TCHUNK 32

typedef unsigned long long u64;

__device__ __forceinline__ u64 pack2(float lo, float hi) {
    u64 r; asm("mov.b64 %0, {%1,%2};" : "=l"(r) : "f"(lo), "f"(hi)); return r;
}
__device__ __forceinline__ void unpack2(u64 v, float &lo, float &hi) {
    asm("mov.b64 {%0,%1}, %2;" : "=f"(lo), "=f"(hi) : "l"(v));
}
__device__ __forceinline__ void fma2(u64 &d, u64 a, u64 b) {
    asm("fma.rn.f32x2 %0, %1, %2, %0;" : "+l"(d) : "l"(a), "l"(b));
}
__device__ __forceinline__ float hsum2(u64 v) {
    float lo, hi; unpack2(v, lo, hi); return lo + hi;
}
__device__ __forceinline__ float fsig(float v) {
    float e; asm("ex2.approx.f32 %0, %1;" : "=f"(e) : "f"(v * -1.4426950408889634f));
    float r; asm("rcp.approx.f32 %0, %1;" : "=f"(r) : "f"(1.0f + e));
    return r;
}
__device__ __forceinline__ float ftanh(float v) {
    return fmaf(2.0f, fsig(2.0f * v), -1.0f);
}

// 512 MB hidden-state scratch: g_h[((b*TT)+t)*HH + u]
__device__ float g_h[(size_t)4096 * TT * HH];

// Shared layout (floats):
//   W  : [0, 12288)   u64-packed interleave: wsh[((g*2+uh)*16+kq)*64 + 2*lane + p]
//   hA : [12288, +2048)   h buffer 0: h[b_local*64 + u]
//   hB : [14336, +2048)   h buffer 1
//   xt : [16384, +2048)   per-group x tiles, 2 bufs: xt[grp*512 + buf*256 + j*32 + tt]
#define OFF_HA 12288
#define OFF_HB 14336
#define OFF_X  16384
#define SMEM_FLOATS 18432

__global__ void __launch_bounds__(NTHREADS, 1)
gru_kernel(const float* __restrict__ x,
           const float* __restrict__ w_ih,
           const float* __restrict__ w_hh,
           const float* __restrict__ b_ih,
           const float* __restrict__ b_hh)
{
    extern __shared__ float smem[];
    u64*   wsh = reinterpret_cast<u64*>(smem);   // 6144 u64
    float* hA  = smem + OFF_HA;
    float* hB  = smem + OFF_HB;
    float* xt  = smem + OFF_X;

    const int tid  = threadIdx.x;
    const int grp  = tid >> 6;          // group 0..3
    const int u    = tid & 63;          // hidden unit within group
    const int uh   = (tid >> 5) & 1;    // unit half (u>=32)
    const int lane = tid & 31;
    const int bL0  = grp * NB;          // local batch base
    const size_t bg = (size_t)blockIdx.x * MB + bL0;  // global batch base (group)
    const int barid = grp + 1;

    // ---- pack W_hh into interleaved conflict-free layout (as R5) ----
    for (int idx = tid; idx < 6144; idx += NTHREADS) {
        const int p   = idx & 1;
        const int ln  = (idx >> 1) & 31;
        const int rst = idx >> 6;
        const int kq  = rst & 15;
        const int guh = rst >> 4;            // 0..5
        const int g   = guh >> 1;
        const int hh  = guh & 1;
        const int uu  = hh * 32 + ln;
        const float2 wv = *reinterpret_cast<const float2*>(
            &w_hh[(g * HH + uu) * HH + 4 * kq + 2 * p]);
        wsh[idx] = pack2(wv.x, wv.y);
    }
    for (int i = tid; i < 4096; i += NTHREADS) hA[i] = 0.0f;   // zeros hA+hB

    // Stage first x chunk (group-local: 8 b x 32 t = 64 float4, 1 per thread)
    {
        int bl = u >> 3, q = u & 7;
        float4 v = *reinterpret_cast<const float4*>(&x[(bg + bl) * TT + q * 4]);
        *reinterpret_cast<float4*>(&xt[grp * 512 + bl * 32 + q * 4]) = v;
    }

    const float wir = w_ih[u], wiz = w_ih[HH + u], win = w_ih[2 * HH + u];
    const float brc = b_ih[u]        + b_hh[u];
    const float bzc = b_ih[HH + u]   + b_hh[HH + u];
    const float bin = b_ih[2 * HH + u];
    const float bhn = b_hh[2 * HH + u];

    const u64* wbase = wsh + uh * 1024 + 2 * lane;   // gate stride 2048, kq stride 64

    float hp[NB];
    #pragma unroll
    for (int j = 0; j < NB; ++j) hp[j] = 0.0f;

    __syncthreads();   // W + zeros + x visible to everyone once

    int p = 0;
    for (int t = 0; t < TT; ++t) {
        const float* hrow = (p ? hB : hA) + bL0 * HH;
        float*       hwro = (p ? hA : hB) + bL0 * HH;

        // ---- GEMM: k-paired f32x2, coalesced W, broadcast h ----
        u64 ar[NB], az[NB], an[NB];
        #pragma unroll
        for (int j = 0; j < NB; ++j) { ar[j] = 0ull; az[j] = 0ull; an[j] = 0ull; }

        #pragma unroll
        for (int kq = 0; kq < 16; ++kq) {
            const ulonglong2 wr = *reinterpret_cast<const ulonglong2*>(wbase + kq * 64);
            const ulonglong2 wz = *reinterpret_cast<const ulonglong2*>(wbase + 2048 + kq * 64);
            const ulonglong2 wn = *reinterpret_cast<const ulonglong2*>(wbase + 4096 + kq * 64);
            ulonglong2 hq[NB];
            #pragma unroll
            for (int j = 0; j < NB; ++j)
                hq[j] = *reinterpret_cast<const ulonglong2*>(&hrow[j * HH + 4 * kq]);
            #pragma unroll
            for (int j = 0; j < NB; ++j) {
                fma2(ar[j], wr.x, hq[j].x); fma2(ar[j], wr.y, hq[j].y);
                fma2(az[j], wz.x, hq[j].x); fma2(az[j], wz.y, hq[j].y);
                fma2(an[j], wn.x, hq[j].x); fma2(an[j], wn.y, hq[j].y);
            }
        }

        // ---- Epilogue: gates, h update, STS + STG (no reductions) ----
        const float* xcur = xt + grp * 512 + ((t >> 5) & 1) * 256;
        const int ttl = t & (TCHUNK - 1);
        #pragma unroll
        for (int j = 0; j < NB; ++j) {
            const float xv = xcur[j * 32 + ttl];
            const float r  = fsig(fmaf(wir, xv, hsum2(ar[j]) + brc));
            const float z  = fsig(fmaf(wiz, xv, hsum2(az[j]) + bzc));
            const float n  = ftanh(fmaf(r, hsum2(an[j]) + bhn, fmaf(win, xv, bin)));
            const float hn = fmaf(z, hp[j] - n, n);
            hp[j] = hn;
            hwro[j * HH + u] = hn;
            g_h[((bg + j) * TT + t) * HH + u] = hn;
        }

        // Stage next x chunk (other buffer; readers wait at the barrier)
        if (((t + 1) & (TCHUNK - 1)) == 0 && (t + 1) < TT) {
            int bl = u >> 3, q = u & 7;
            float4 v = *reinterpret_cast<const float4*>(
                &x[(bg + bl) * TT + (t + 1) + q * 4]);
            float* xnext = xt + grp * 512 + (((t + 1) >> 5) & 1) * 256;
            *reinterpret_cast<float4*>(&xnext[bl * 32 + q * 4]) = v;
        }

        // Per-group named barrier: publish h(t+1) within the 64-thread group
        asm volatile("bar.sync %0, %1;" :: "r"(barid), "r"(64) : "memory");
        p ^= 1;
    }
}

// out[b*TT + t] = dot(g_h[(b*TT+t)*64 .. +64), w_lin) + b_lin
__global__ void __launch_bounds__(256)
out_kernel(const float* __restrict__ w_lin,
           const float* __restrict__ b_lin,
           float* __restrict__ out)
{
    __shared__ float wsl[HH];
    if (threadIdx.x < HH) wsl[threadIdx.x] = w_lin[threadIdx.x];
    __syncthreads();
    const float blv = b_lin[0];

    const size_t idx = (size_t)blockIdx.x * blockDim.x + threadIdx.x;  // b*TT + t
    const float* hp = &g_h[idx * HH];

    float a0 = 0.f, a1 = 0.f, a2 = 0.f, a3 = 0.f;
    #pragma unroll
    for (int q = 0; q < 16; ++q) {
        const float4 h4 = *reinterpret_cast<const float4*>(hp + 4 * q);
        a0 = fmaf(h4.x, wsl[4 * q + 0], a0);
        a1 = fmaf(h4.y, wsl[4 * q + 1], a1);
        a2 = fmaf(h4.z, wsl[4 * q + 2], a2);
        a3 = fmaf(h4.w, wsl[4 * q + 3], a3);
    }
    out[idx] = (a0 + a1) + (a2 + a3) + blv;
}

extern "C" void kernel_launch(void* const* d_in, const int* in_sizes, int n_in,
                              void* d_out, int out_size) {
    const float* x     = (const float*)d_in[0];
    const float* w_ih  = (const float*)d_in[1];
    const float* w_hh  = (const float*)d_in[2];
    const float* b_ih  = (const float*)d_in[3];
    const float* b_hh  = (const float*)d_in[4];
    const float* w_lin = (const float*)d_in[5];
    const float* b_lin = (const float*)d_in[6];
    float* out = (float*)d_out;

    const size_t smem_bytes = SMEM_FLOATS * sizeof(float);
    cudaFuncSetAttribute(gru_kernel, cudaFuncAttributeMaxDynamicSharedMemorySize,
                         (int)smem_bytes);
    gru_kernel<<<4096 / MB, NTHREADS, smem_bytes>>>(x, w_ih, w_hh, b_ih, b_hh);
    out_kernel<<<(4096 * TT) / 256, 256>>>(w_lin, b_lin, out);
}

// round 8
// speedup vs baseline: 1.0163x; 1.0163x over previous
#include <cuda_runtime.h>

// GRU_39170101739852: B=4096, T=512, H=64 GRU + Linear(H->1), fp32.
// R8: warp = autonomous GRU engine for 8 batches x all 64 units (NU=2:
// lane owns units u and u+32). Halves smem h-traffic, no barriers at all
// (warp-synchronous), output Linear folded in via designated lanes.

#define TT 512
#define HH 64
#define MB 32
#define NTH 128
#define NB 8
#define PH 68          // h row pitch (rows bank-staggered, 16B aligned)
#define TCHUNK 32

typedef unsigned long long u64;

__device__ __forceinline__ u64 pack2(float lo, float hi) {
    u64 r; asm("mov.b64 %0, {%1,%2};" : "=l"(r) : "f"(lo), "f"(hi)); return r;
}
__device__ __forceinline__ void unpack2(u64 v, float &lo, float &hi) {
    asm("mov.b64 {%0,%1}, %2;" : "=f"(lo), "=f"(hi) : "l"(v));
}
__device__ __forceinline__ void fma2(u64 &d, u64 a, u64 b) {
    asm("fma.rn.f32x2 %0, %1, %2, %0;" : "+l"(d) : "l"(a), "l"(b));
}
__device__ __forceinline__ float hsum2(u64 v) {
    float lo, hi; unpack2(v, lo, hi); return lo + hi;
}
__device__ __forceinline__ float fsig(float v) {
    float e; asm("ex2.approx.f32 %0, %1;" : "=f"(e) : "f"(v * -1.4426950408889634f));
    float r; asm("rcp.approx.f32 %0, %1;" : "=f"(r) : "f"(1.0f + e));
    return r;
}
__device__ __forceinline__ float ftanh(float v) {
    return fmaf(2.0f, fsig(2.0f * v), -1.0f);
}

// Shared layout (floats):
//   W   : [0, 12288)        u64-packed: wsh[((g*2+uh)*16+kq)*64 + 2*lane + p]
//   hA  : [12288, +2176)    h buffer 0: 32 rows x pitch 68
//   hB  : [14464, +2176)    h buffer 1
//   xt  : [16640, +2048)    x tiles: 2 bufs x 32 rows x 32
//   wlp : [18688, +64)      w_lin packed as 32 u64
#define OFF_HA 12288
#define OFF_HB 14464
#define OFF_X  16640
#define OFF_WL 18688
#define SMEM_FLOATS 18752

__global__ void __launch_bounds__(NTH, 1)
gru_kernel(const float* __restrict__ x,
           const float* __restrict__ w_ih,
           const float* __restrict__ w_hh,
           const float* __restrict__ b_ih,
           const float* __restrict__ b_hh,
           const float* __restrict__ w_lin,
           const float* __restrict__ b_lin,
           float* __restrict__ out)
{
    extern __shared__ float smem[];
    u64*   wsh = reinterpret_cast<u64*>(smem);
    float* hA  = smem + OFF_HA;
    float* hB  = smem + OFF_HB;
    float* xt  = smem + OFF_X;
    u64*   wlp = reinterpret_cast<u64*>(smem + OFF_WL);

    const int tid  = threadIdx.x;
    const int lane = tid & 31;
    const int wrp  = tid >> 5;
    const int row0 = wrp * NB;                       // CTA-local batch base
    const size_t bgw = (size_t)blockIdx.x * MB + row0;
    const int u0 = lane, u1 = lane + 32;

    // ---- pack W_hh (interleaved conflict-free layout, as R5/R7) ----
    for (int idx = tid; idx < 6144; idx += NTH) {
        const int pp  = idx & 1;
        const int ln  = (idx >> 1) & 31;
        const int rst = idx >> 6;
        const int kq  = rst & 15;
        const int guh = rst >> 4;            // 0..5 = g*2 + uh
        const int g   = guh >> 1;
        const int hh  = guh & 1;
        const int uu  = hh * 32 + ln;
        const float2 wv = *reinterpret_cast<const float2*>(
            &w_hh[(g * HH + uu) * HH + 4 * kq + 2 * pp]);
        wsh[idx] = pack2(wv.x, wv.y);
    }
    for (int i = tid; i < 2 * 2176; i += NTH) hA[i] = 0.0f;   // hA + hB

    // First x chunk: 32 rows x 32 t = 256 float4
    for (int i = tid; i < 256; i += NTH) {
        int bl = i >> 3, q = i & 7;
        float4 v = *reinterpret_cast<const float4*>(
            &x[((size_t)blockIdx.x * MB + bl) * TT + q * 4]);
        *reinterpret_cast<float4*>(&xt[bl * 32 + q * 4]) = v;
    }
    if (tid < 32) wlp[tid] = pack2(w_lin[2 * tid], w_lin[2 * tid + 1]);

    // Biases / input weights for both owned units
    float wir[2], wiz[2], win[2], brc[2], bzc[2], bin[2], bhn[2];
    {
        const int us[2] = {u0, u1};
        #pragma unroll
        for (int e = 0; e < 2; ++e) {
            const int uu = us[e];
            wir[e] = w_ih[uu]; wiz[e] = w_ih[HH + uu]; win[e] = w_ih[2 * HH + uu];
            brc[e] = b_ih[uu] + b_hh[uu];
            bzc[e] = b_ih[HH + uu] + b_hh[HH + uu];
            bin[e] = b_ih[2 * HH + uu];
            bhn[e] = b_hh[2 * HH + uu];
        }
    }
    const float blv = b_lin[0];

    const u64* pw[6];
    #pragma unroll
    for (int guh = 0; guh < 6; ++guh) pw[guh] = wsh + guh * 1024 + 2 * lane;

    float hpA[NB], hpB[NB];
    #pragma unroll
    for (int j = 0; j < NB; ++j) { hpA[j] = 0.0f; hpB[j] = 0.0f; }

    __syncthreads();   // init visible; after this, warps run free

    int p = 0;
    for (int t = 0; t < TT; ++t) {
        const float* hr = (p ? hB : hA) + row0 * PH;
        float*       hw = (p ? hA : hB) + row0 * PH;
        const float* xcur = xt + ((t >> 5) & 1) * 1024 + row0 * 32;
        const int ttl = t & 31;

        // ---- out[t-1] for this warp's 8 batches (lanes 0..7, conflict-free) ----
        if (t > 0 && lane < NB) {
            const float* hx = hr + lane * PH;
            u64 acc = 0ull;
            #pragma unroll
            for (int i = 0; i < 16; ++i) {
                ulonglong2 h2 = *reinterpret_cast<const ulonglong2*>(hx + 4 * i);
                ulonglong2 w2 = *reinterpret_cast<const ulonglong2*>(wlp + 2 * i);
                fma2(acc, w2.x, h2.x); fma2(acc, w2.y, h2.y);
            }
            out[(bgw + lane) * TT + (t - 1)] = hsum2(acc) + blv;
        }

        // ---- GEMM: 3 gates x 2 units x 8 batches, k-paired f32x2 ----
        u64 aA[3][NB], aB[3][NB];
        #pragma unroll
        for (int g = 0; g < 3; ++g)
            #pragma unroll
            for (int j = 0; j < NB; ++j) { aA[g][j] = 0ull; aB[g][j] = 0ull; }

        #pragma unroll 8
        for (int kq = 0; kq < 16; ++kq) {
            ulonglong2 wg[6];
            #pragma unroll
            for (int guh = 0; guh < 6; ++guh)
                wg[guh] = *reinterpret_cast<const ulonglong2*>(pw[guh] + kq * 64);
            #pragma unroll
            for (int j = 0; j < NB; ++j) {
                const ulonglong2 hq =
                    *reinterpret_cast<const ulonglong2*>(hr + j * PH + 4 * kq);
                fma2(aA[0][j], wg[0].x, hq.x); fma2(aA[0][j], wg[0].y, hq.y);
                fma2(aB[0][j], wg[1].x, hq.x); fma2(aB[0][j], wg[1].y, hq.y);
                fma2(aA[1][j], wg[2].x, hq.x); fma2(aA[1][j], wg[2].y, hq.y);
                fma2(aB[1][j], wg[3].x, hq.x); fma2(aB[1][j], wg[3].y, hq.y);
                fma2(aA[2][j], wg[4].x, hq.x); fma2(aA[2][j], wg[4].y, hq.y);
                fma2(aB[2][j], wg[5].x, hq.x); fma2(aB[2][j], wg[5].y, hq.y);
            }
        }

        // ---- Epilogue: both units, 8 batches ----
        #pragma unroll
        for (int j = 0; j < NB; ++j) {
            const float xv = xcur[j * 32 + ttl];
            {
                const float r = fsig(fmaf(wir[0], xv, hsum2(aA[0][j]) + brc[0]));
                const float z = fsig(fmaf(wiz[0], xv, hsum2(aA[1][j]) + bzc[0]));
                const float n = ftanh(fmaf(r, hsum2(aA[2][j]) + bhn[0],
                                           fmaf(win[0], xv, bin[0])));
                const float hn = fmaf(z, hpA[j] - n, n);
                hpA[j] = hn;
                hw[j * PH + u0] = hn;
            }
            {
                const float r = fsig(fmaf(wir[1], xv, hsum2(aB[0][j]) + brc[1]));
                const float z = fsig(fmaf(wiz[1], xv, hsum2(aB[1][j]) + bzc[1]));
                const float n = ftanh(fmaf(r, hsum2(aB[2][j]) + bhn[1],
                                           fmaf(win[1], xv, bin[1])));
                const float hn = fmaf(z, hpB[j] - n, n);
                hpB[j] = hn;
                hw[j * PH + u1] = hn;
            }
        }

        // ---- Stage next x chunk (warp-local rows) ----
        if (((t + 1) & 31) == 0 && (t + 1) < TT) {
            #pragma unroll
            for (int i = lane; i < 64; i += 32) {
                const int bl = i >> 3, q = i & 7;
                const float4 v = *reinterpret_cast<const float4*>(
                    &x[(bgw + bl) * TT + (t + 1) + q * 4]);
                float* xn = xt + (((t + 1) >> 5) & 1) * 1024 + (row0 + bl) * 32;
                *reinterpret_cast<float4*>(&xn[q * 4]) = v;
            }
        }

        __syncwarp();
        p ^= 1;
    }

    // final out[TT-1] from the last-written buffer
    if (lane < NB) {
        const float* hx = (p ? hB : hA) + (row0 + lane) * PH;
        u64 acc = 0ull;
        #pragma unroll
        for (int i = 0; i < 16; ++i) {
            ulonglong2 h2 = *reinterpret_cast<const ulonglong2*>(hx + 4 * i);
            ulonglong2 w2 = *reinterpret_cast<const ulonglong2*>(wlp + 2 * i);
            fma2(acc, w2.x, h2.x); fma2(acc, w2.y, h2.y);
        }
        out[(bgw + lane) * TT + (TT - 1)] = hsum2(acc) + blv;
    }
}

extern "C" void kernel_launch(void* const* d_in, const int* in_sizes, int n_in,
                              void* d_out, int out_size) {
    const float* x     = (const float*)d_in[0];
    const float* w_ih  = (const float*)d_in[1];
    const float* w_hh  = (const float*)d_in[2];
    const float* b_ih  = (const float*)d_in[3];
    const float* b_hh  = (const float*)d_in[4];
    const float* w_lin = (const float*)d_in[5];
    const float* b_lin = (const float*)d_in[6];
    float* out = (float*)d_out;

    const size_t smem_bytes = SMEM_FLOATS * sizeof(float);
    cudaFuncSetAttribute(gru_kernel, cudaFuncAttributeMaxDynamicSharedMemorySize,
                         (int)smem_bytes);
    gru_kernel<<<4096 / MB, NTH, smem_bytes>>>(x, w_ih, w_hh, b_ih, b_hh,
                                               w_lin, b_lin, out);
}

// round 10
// speedup vs baseline: 2.3590x; 2.3210x over previous
#include <cuda_runtime.h>
#include <cuda_bf16.h>
#include <cstdint>

// GRU_39170101739852: B=4096, T=512, H=64 GRU + Linear(H->1), fp32.
// R10: legacy mma.sync (m16n8k16 bf16, fp32 acc) split-precision GRU.
//   D[192 gates][16 batches] = (Whi+Wlo) @ (hhi+hlo)^T, 3-term.
//   2 independent 128-thread engines per CTA, A-frags register-resident,
//   gate planes bounced via smem, biases folded into accumulator init.

#define TT 512
#define HH 64
#define NTH 256
#define ESTR 21888   // per-engine smem stride (bytes)

__device__ __forceinline__ float fsig(float v) {
    float e; asm("ex2.approx.f32 %0, %1;" : "=f"(e) : "f"(v * -1.4426950408889634f));
    float r; asm("rcp.approx.f32 %0, %1;" : "=f"(r) : "f"(1.0f + e));
    return r;
}
__device__ __forceinline__ float ftanh(float v) {
    return fmaf(2.0f, fsig(2.0f * v), -1.0f);
}
__device__ __forceinline__ uint32_t pkbf(float a, float b) {
    const __nv_bfloat16 x = __float2bfloat16(a);
    const __nv_bfloat16 y = __float2bfloat16(b);
    return (uint32_t)*(const uint16_t*)&x | ((uint32_t)*(const uint16_t*)&y << 16);
}

#define MMA(d, a, bb) \
    asm volatile("mma.sync.aligned.m16n8k16.row.col.f32.bf16.bf16.f32 " \
        "{%0,%1,%2,%3}, {%4,%5,%6,%7}, {%8,%9}, {%0,%1,%2,%3};" \
        : "+f"((d)[0]), "+f"((d)[1]), "+f"((d)[2]), "+f"((d)[3]) \
        : "r"((a)[0]), "r"((a)[1]), "r"((a)[2]), "r"((a)[3]), \
          "r"((bb)[0]), "r"((bb)[1]))

// Per-engine smem layout (byte offsets within engine block):
//   hhi : [0, 2304)      h hi tile: [16 batches][72 bf16] (pitch 144B)
//   hlo : [2304, 4608)   h lo tile
//   pln : [4608, 17664)  3 gate planes (r,z,n), each [16][68] f32 (4352B)
//   xt  : [17664, 21888) x tiles: [2][16][33] f32

__global__ void __launch_bounds__(NTH, 1)
gru_mma_kernel(const float* __restrict__ x,
               const float* __restrict__ w_ih,
               const float* __restrict__ w_hh,
               const float* __restrict__ b_ih,
               const float* __restrict__ b_hh,
               const float* __restrict__ w_lin,
               const float* __restrict__ b_lin,
               float* __restrict__ out)
{
    extern __shared__ char smem[];
    const int tid  = threadIdx.x;
    const int eng  = tid >> 7;          // engine (warpgroup) 0/1
    const int wt   = tid & 127;
    const int w    = (tid >> 5) & 3;    // warp within engine
    const int lane = tid & 31;
    const int g    = lane >> 2;         // groupID
    const int tig  = lane & 3;          // thread-in-group
    const int bgw  = blockIdx.x * 32 + eng * 16;

    char*  E   = smem + eng * ESTR;
    char*  hhi = E;
    char*  hlo = E + 2304;
    float* pln = (float*)(E + 4608);
    float* xt  = (float*)(E + 17664);
    const int barid = eng + 1;

    // zero h tiles (hhi+hlo = 4608 B = 1152 u32)
    for (int i = wt; i < 1152; i += 128) ((uint32_t*)E)[i] = 0u;

    // stage x chunk 0: 16 rows x 32 t
    {
        const int bl = wt >> 3, q = wt & 7;
        const float4 v = *(const float4*)&x[(size_t)(bgw + bl) * TT + q * 4];
        float* xp = xt + bl * 33 + q * 4;
        xp[0] = v.x; xp[1] = v.y; xp[2] = v.z; xp[3] = v.w;
    }

    // ---- A fragments (register-resident W, split hi/lo) + bias init ----
    uint32_t ahi[3][4][4], alo[3][4][4];
    float biasA[3], biasB[3];
    #pragma unroll
    for (int mt = 0; mt < 3; ++mt) {
        const int rA = 48 * w + 16 * mt + g;
        const int rB = rA + 8;
        biasA[mt] = (rA < 128) ? (b_ih[rA] + b_hh[rA]) : b_hh[rA];
        biasB[mt] = (rB < 128) ? (b_ih[rB] + b_hh[rB]) : b_hh[rB];
        #pragma unroll
        for (int ks = 0; ks < 4; ++ks) {
            #pragma unroll
            for (int pos = 0; pos < 4; ++pos) {
                const int row = (pos & 1) ? rB : rA;
                const int col = 16 * ks + 2 * tig + ((pos >> 1) * 8);
                const float f0 = w_hh[row * HH + col];
                const float f1 = w_hh[row * HH + col + 1];
                const __nv_bfloat16 h0 = __float2bfloat16(f0);
                const __nv_bfloat16 h1 = __float2bfloat16(f1);
                ahi[mt][ks][pos] = pkbf(f0, f1);
                alo[mt][ks][pos] = pkbf(f0 - __bfloat162float(h0),
                                        f1 - __bfloat162float(h1));
            }
        }
    }

    // ---- epilogue params: thread owns batch b, units u0..u0+7 ----
    const int b  = wt >> 3;
    const int u0 = (wt & 7) * 8;
    float wir[8], wiz[8], win[8], binv[8], wl[8], hp[8];
    #pragma unroll
    for (int du = 0; du < 8; ++du) {
        const int u = u0 + du;
        wir[du]  = w_ih[u];
        wiz[du]  = w_ih[HH + u];
        win[du]  = w_ih[2 * HH + u];
        binv[du] = b_ih[2 * HH + u];
        wl[du]   = w_lin[u];
        hp[du]   = 0.0f;
    }
    const float blv = b_lin[0];

    __syncthreads();

    #pragma unroll 1
    for (int t = 0; t < TT; ++t) {
        // ---- B fragments from h tiles (conflict-free LDS.32) ----
        uint32_t bh[2][4][2], bl2[2][4][2];
        #pragma unroll
        for (int nt = 0; nt < 2; ++nt) {
            #pragma unroll
            for (int ks = 0; ks < 4; ++ks) {
                const int off = (8 * nt + g) * 144 + ks * 32 + tig * 4;
                bh[nt][ks][0]  = *(const uint32_t*)(hhi + off);
                bh[nt][ks][1]  = *(const uint32_t*)(hhi + off + 16);
                bl2[nt][ks][0] = *(const uint32_t*)(hlo + off);
                bl2[nt][ks][1] = *(const uint32_t*)(hlo + off + 16);
            }
        }

        // ---- accumulators = bias, then 3-term MMA ----
        float acc[3][2][4];
        #pragma unroll
        for (int mt = 0; mt < 3; ++mt)
            #pragma unroll
            for (int nt = 0; nt < 2; ++nt) {
                acc[mt][nt][0] = biasA[mt]; acc[mt][nt][1] = biasA[mt];
                acc[mt][nt][2] = biasB[mt]; acc[mt][nt][3] = biasB[mt];
            }
        #pragma unroll
        for (int mt = 0; mt < 3; ++mt)
            #pragma unroll
            for (int nt = 0; nt < 2; ++nt)
                #pragma unroll
                for (int ks = 0; ks < 4; ++ks) {
                    MMA(acc[mt][nt], ahi[mt][ks], bh[nt][ks]);
                    MMA(acc[mt][nt], ahi[mt][ks], bl2[nt][ks]);
                    MMA(acc[mt][nt], alo[mt][ks], bh[nt][ks]);
                }

        // ---- scatter to gate planes [batch][unit], pitch 68 ----
        #pragma unroll
        for (int mt = 0; mt < 3; ++mt) {
            const int rb = 48 * w + 16 * mt;
            float* pp = pln + (rb >> 6) * 1088 + (rb & 63) + g;
            #pragma unroll
            for (int nt = 0; nt < 2; ++nt) {
                const int c0 = 8 * nt + 2 * tig;
                pp[c0 * 68]           = acc[mt][nt][0];
                pp[(c0 + 1) * 68]     = acc[mt][nt][1];
                pp[c0 * 68 + 8]       = acc[mt][nt][2];
                pp[(c0 + 1) * 68 + 8] = acc[mt][nt][3];
            }
        }
        asm volatile("bar.sync %0, 128;" :: "r"(barid) : "memory");

        // ---- epilogue: 8 units of batch b ----
        const float xv = xt[((t >> 5) & 1) * 528 + b * 33 + (t & 31)];
        float rv[8], zv[8], nv[8];
        {
            const float* p0 = pln + b * 68 + u0;
            const float* p1 = pln + 1088 + b * 68 + u0;
            const float* p2 = pln + 2176 + b * 68 + u0;
            const float4 a0 = *(const float4*)p0, a1 = *(const float4*)(p0 + 4);
            rv[0]=a0.x; rv[1]=a0.y; rv[2]=a0.z; rv[3]=a0.w;
            rv[4]=a1.x; rv[5]=a1.y; rv[6]=a1.z; rv[7]=a1.w;
            const float4 c0 = *(const float4*)p1, c1 = *(const float4*)(p1 + 4);
            zv[0]=c0.x; zv[1]=c0.y; zv[2]=c0.z; zv[3]=c0.w;
            zv[4]=c1.x; zv[5]=c1.y; zv[6]=c1.z; zv[7]=c1.w;
            const float4 e0 = *(const float4*)p2, e1 = *(const float4*)(p2 + 4);
            nv[0]=e0.x; nv[1]=e0.y; nv[2]=e0.z; nv[3]=e0.w;
            nv[4]=e1.x; nv[5]=e1.y; nv[6]=e1.z; nv[7]=e1.w;
        }
        float hn[8], s = 0.0f;
        #pragma unroll
        for (int du = 0; du < 8; ++du) {
            const float r = fsig(fmaf(wir[du], xv, rv[du]));       // bias in acc
            const float z = fsig(fmaf(wiz[du], xv, zv[du]));       // bias in acc
            const float n = ftanh(fmaf(r, nv[du], fmaf(win[du], xv, binv[du])));
            const float h = fmaf(z, hp[du] - n, n);
            hp[du] = h; hn[du] = h;
            s = fmaf(wl[du], h, s);
        }

        // ---- store h hi/lo for next step's B tiles ----
        uint32_t hw[4], lw[4];
        #pragma unroll
        for (int q = 0; q < 4; ++q) {
            const float f0 = hn[2 * q], f1 = hn[2 * q + 1];
            const __nv_bfloat16 h0 = __float2bfloat16(f0);
            const __nv_bfloat16 h1 = __float2bfloat16(f1);
            hw[q] = pkbf(f0, f1);
            lw[q] = pkbf(f0 - __bfloat162float(h0), f1 - __bfloat162float(h1));
        }
        *(uint4*)(hhi + b * 144 + u0 * 2) = make_uint4(hw[0], hw[1], hw[2], hw[3]);
        *(uint4*)(hlo + b * 144 + u0 * 2) = make_uint4(lw[0], lw[1], lw[2], lw[3]);

        // ---- output dot over the 8 unit-threads of batch b ----
        s += __shfl_xor_sync(0xffffffffu, s, 1);
        s += __shfl_xor_sync(0xffffffffu, s, 2);
        s += __shfl_xor_sync(0xffffffffu, s, 4);
        if ((wt & 7) == 0)
            out[(size_t)(bgw + b) * TT + t] = s + blv;

        // ---- stage next x chunk ----
        if (((t + 1) & 31) == 0 && (t + 1) < TT) {
            const int bl = wt >> 3, q = wt & 7;
            const float4 v = *(const float4*)&x[(size_t)(bgw + bl) * TT + (t + 1) + q * 4];
            float* xp = xt + (((t + 1) >> 5) & 1) * 528 + bl * 33 + q * 4;
            xp[0] = v.x; xp[1] = v.y; xp[2] = v.z; xp[3] = v.w;
        }
        asm volatile("bar.sync %0, 128;" :: "r"(barid) : "memory");
    }
}

extern "C" void kernel_launch(void* const* d_in, const int* in_sizes, int n_in,
                              void* d_out, int out_size) {
    const float* x     = (const float*)d_in[0];
    const float* w_ih  = (const float*)d_in[1];
    const float* w_hh  = (const float*)d_in[2];
    const float* b_ih  = (const float*)d_in[3];
    const float* b_hh  = (const float*)d_in[4];
    const float* w_lin = (const float*)d_in[5];
    const float* b_lin = (const float*)d_in[6];
    float* out = (float*)d_out;

    const int smem_bytes = 2 * ESTR;   // 43776
    cudaFuncSetAttribute(gru_mma_kernel, cudaFuncAttributeMaxDynamicSharedMemorySize,
                         smem_bytes);
    gru_mma_kernel<<<128, NTH, smem_bytes>>>(x, w_ih, w_hh, b_ih, b_hh,
                                             w_lin, b_lin, out);
}

// round 11
// speedup vs baseline: 3.3445x; 1.4178x over previous
#include <cuda_runtime.h>
#include <cuda_bf16.h>
#include <cstdint>

// GRU_39170101739852: B=4096, T=512, H=64 GRU + Linear(H->1), fp32.
// R11: mma.sync bf16 split-precision GRU, gate-aligned warp ownership.
//   Warp w computes gates r,z,n for ITS 16 units (m-tiles rows u,64+u,128+u)
//   -> epilogue fully in registers: no plane bounce, 1 barrier/step,
//   tanh.approx MUFU (24/thread). h tiles double-buffered bf16 hi/lo.

#define TT 512
#define HH 64
#define NTH 256
#define PITCH 144        // bytes per batch row in h tile (72 bf16)
#define HBUF 4608        // one h buffer: hhi(2304) + hlo(2304)
#define O_X  9216        // x tiles: 2 x 16 x 33 f32 = 4224 B
#define O_RED 13440      // red: 2 x 16 x 4 f32 = 512 B
#define ESTR 13952       // per-engine smem stride

__device__ __forceinline__ float ftanh(float v) {
    float r; asm("tanh.approx.f32 %0, %1;" : "=f"(r) : "f"(v)); return r;
}
__device__ __forceinline__ float fsig(float v) {
    return fmaf(0.5f, ftanh(0.5f * v), 0.5f);
}
__device__ __forceinline__ uint32_t pkbf(float a, float b) {
    const __nv_bfloat16 x = __float2bfloat16(a);
    const __nv_bfloat16 y = __float2bfloat16(b);
    return (uint32_t)*(const uint16_t*)&x | ((uint32_t)*(const uint16_t*)&y << 16);
}

#define MMA(d, a, bb) \
    asm volatile("mma.sync.aligned.m16n8k16.row.col.f32.bf16.bf16.f32 " \
        "{%0,%1,%2,%3}, {%4,%5,%6,%7}, {%8,%9}, {%0,%1,%2,%3};" \
        : "+f"((d)[0]), "+f"((d)[1]), "+f"((d)[2]), "+f"((d)[3]) \
        : "r"((a)[0]), "r"((a)[1]), "r"((a)[2]), "r"((a)[3]), \
          "r"((bb)[0]), "r"((bb)[1]))

__global__ void __launch_bounds__(NTH, 1)
gru_mma_kernel(const float* __restrict__ x,
               const float* __restrict__ w_ih,
               const float* __restrict__ w_hh,
               const float* __restrict__ b_ih,
               const float* __restrict__ b_hh,
               const float* __restrict__ w_lin,
               const float* __restrict__ b_lin,
               float* __restrict__ out)
{
    extern __shared__ char smem[];
    const int tid  = threadIdx.x;
    const int eng  = tid >> 7;           // engine 0/1 (16 batches each)
    const int wt   = tid & 127;
    const int w    = (tid >> 5) & 3;     // warp in engine: units 16w..16w+15
    const int lane = tid & 31;
    const int g    = lane >> 2;
    const int tig  = lane & 3;
    const int bgw  = blockIdx.x * 32 + eng * 16;
    const int barid = eng + 1;

    char*  E   = smem + eng * ESTR;
    float* xt  = (float*)(E + O_X);
    float* red = (float*)(E + O_RED);

    // zero both h buffers (2*4608 B = 2304 words)
    for (int i = wt; i < 2304; i += 128) ((uint32_t*)E)[i] = 0u;

    // stage x chunk 0
    {
        const int bl = wt >> 3, q = wt & 7;
        const float4 v = *(const float4*)&x[(size_t)(bgw + bl) * TT + q * 4];
        float* xp = xt + bl * 33 + q * 4;
        xp[0] = v.x; xp[1] = v.y; xp[2] = v.z; xp[3] = v.w;
    }

    // ---- A fragments: warp w, m-tile mt = gate mt, rows = gate block + own units ----
    const int uA = 16 * w + g, uB = uA + 8;
    uint32_t ahi[3][4][4], alo[3][4][4];
    float biasA[3], biasB[3];
    #pragma unroll
    for (int mt = 0; mt < 3; ++mt) {
        const int rA = mt * 64 + uA;
        const int rB = mt * 64 + uB;
        biasA[mt] = (mt < 2) ? (b_ih[rA] + b_hh[rA]) : b_hh[rA];
        biasB[mt] = (mt < 2) ? (b_ih[rB] + b_hh[rB]) : b_hh[rB];
        #pragma unroll
        for (int ks = 0; ks < 4; ++ks) {
            #pragma unroll
            for (int pos = 0; pos < 4; ++pos) {
                const int row = (pos & 1) ? rB : rA;
                const int col = 16 * ks + 2 * tig + ((pos >> 1) * 8);
                const float f0 = w_hh[row * HH + col];
                const float f1 = w_hh[row * HH + col + 1];
                const __nv_bfloat16 h0 = __float2bfloat16(f0);
                const __nv_bfloat16 h1 = __float2bfloat16(f1);
                ahi[mt][ks][pos] = pkbf(f0, f1);
                alo[mt][ks][pos] = pkbf(f0 - __bfloat162float(h0),
                                        f1 - __bfloat162float(h1));
            }
        }
    }

    // per-thread epilogue params for units uA (e=0), uB (e=1)
    float wir[2], wiz[2], win[2], binv[2], wl[2];
    #pragma unroll
    for (int e = 0; e < 2; ++e) {
        const int u = e ? uB : uA;
        wir[e]  = w_ih[u];
        wiz[e]  = w_ih[HH + u];
        win[e]  = w_ih[2 * HH + u];
        binv[e] = b_ih[2 * HH + u];
        wl[e]   = w_lin[u];
    }
    const float blv = b_lin[0];

    float hp[2][2][2];   // [e][nt][jj]
    #pragma unroll
    for (int e = 0; e < 2; ++e)
        #pragma unroll
        for (int nt = 0; nt < 2; ++nt) { hp[e][nt][0] = 0.f; hp[e][nt][1] = 0.f; }

    __syncthreads();

    int p = 0;
    #pragma unroll 1
    for (int t = 0; t < TT; ++t) {
        char* hr  = E + p * HBUF;          // read tile (hhi @0, hlo @2304)
        char* hwt = E + (p ^ 1) * HBUF;    // write tile

        // ---- B fragments ----
        uint32_t bh[2][4][2], bl2[2][4][2];
        #pragma unroll
        for (int nt = 0; nt < 2; ++nt)
            #pragma unroll
            for (int ks = 0; ks < 4; ++ks) {
                const int off = (8 * nt + g) * PITCH + ks * 32 + tig * 4;
                bh[nt][ks][0]  = *(const uint32_t*)(hr + off);
                bh[nt][ks][1]  = *(const uint32_t*)(hr + off + 16);
                bl2[nt][ks][0] = *(const uint32_t*)(hr + 2304 + off);
                bl2[nt][ks][1] = *(const uint32_t*)(hr + 2304 + off + 16);
            }

        // ---- accumulators = bias; 3-term MMA ----
        float acc[3][2][4];
        #pragma unroll
        for (int mt = 0; mt < 3; ++mt)
            #pragma unroll
            for (int nt = 0; nt < 2; ++nt) {
                acc[mt][nt][0] = biasA[mt]; acc[mt][nt][1] = biasA[mt];
                acc[mt][nt][2] = biasB[mt]; acc[mt][nt][3] = biasB[mt];
            }
        #pragma unroll
        for (int mt = 0; mt < 3; ++mt)
            #pragma unroll
            for (int nt = 0; nt < 2; ++nt)
                #pragma unroll
                for (int ks = 0; ks < 4; ++ks) {
                    MMA(acc[mt][nt], ahi[mt][ks], bh[nt][ks]);
                    MMA(acc[mt][nt], ahi[mt][ks], bl2[nt][ks]);
                    MMA(acc[mt][nt], alo[mt][ks], bh[nt][ks]);
                }

        // ---- in-register epilogue: cells (e, nt, jj) ----
        const float* xb = xt + ((t >> 5) & 1) * 528;
        const int ttl = t & 31;
        float s[2][2];   // [nt][jj] output partials (sum over e)
        #pragma unroll
        for (int nt = 0; nt < 2; ++nt)
            #pragma unroll
            for (int jj = 0; jj < 2; ++jj) {
                const int b  = 8 * nt + 2 * tig + jj;
                const float xv = xb[b * 33 + ttl];
                float sv = 0.0f;
                #pragma unroll
                for (int e = 0; e < 2; ++e) {
                    const float ga = acc[0][nt][2 * e + jj];
                    const float gz = acc[1][nt][2 * e + jj];
                    const float gn = acc[2][nt][2 * e + jj];
                    const float r  = fsig(fmaf(wir[e], xv, ga));
                    const float z  = fsig(fmaf(wiz[e], xv, gz));
                    const float n  = ftanh(fmaf(r, gn, fmaf(win[e], xv, binv[e])));
                    const float h  = fmaf(z, hp[e][nt][jj] - n, n);
                    hp[e][nt][jj] = h;
                    sv = fmaf(wl[e], h, sv);
                    // store bf16 hi/lo for next step
                    const int u = e ? uB : uA;
                    const __nv_bfloat16 hb = __float2bfloat16(h);
                    const __nv_bfloat16 lb =
                        __float2bfloat16(h - __bfloat162float(hb));
                    *(__nv_bfloat16*)(hwt + b * PITCH + u * 2)        = hb;
                    *(__nv_bfloat16*)(hwt + 2304 + b * PITCH + u * 2) = lb;
                }
                s[nt][jj] = sv;
            }

        // ---- output partials: reduce over g (units within warp) ----
        #pragma unroll
        for (int off = 4; off <= 16; off <<= 1) {
            s[0][0] += __shfl_xor_sync(0xffffffffu, s[0][0], off);
            s[0][1] += __shfl_xor_sync(0xffffffffu, s[0][1], off);
            s[1][0] += __shfl_xor_sync(0xffffffffu, s[1][0], off);
            s[1][1] += __shfl_xor_sync(0xffffffffu, s[1][1], off);
        }
        float* rcur = red + (t & 1) * 64;
        if (g == 0) {
            #pragma unroll
            for (int nt = 0; nt < 2; ++nt)
                #pragma unroll
                for (int jj = 0; jj < 2; ++jj)
                    rcur[(8 * nt + 2 * tig + jj) * 4 + w] = s[nt][jj];
        }

        // ---- stage next x chunk ----
        if (((t + 1) & 31) == 0 && (t + 1) < TT) {
            const int bl = wt >> 3, q = wt & 7;
            const float4 v = *(const float4*)&x[(size_t)(bgw + bl) * TT + (t + 1) + q * 4];
            float* xp = xt + (((t + 1) >> 5) & 1) * 528 + bl * 33 + q * 4;
            xp[0] = v.x; xp[1] = v.y; xp[2] = v.z; xp[3] = v.w;
        }

        asm volatile("bar.sync %0, 128;" :: "r"(barid) : "memory");

        // ---- out[t] by 16 threads ----
        if (wt < 16) {
            const float4 r4 = *(const float4*)&rcur[wt * 4];
            out[(size_t)(bgw + wt) * TT + t] = (r4.x + r4.y) + (r4.z + r4.w) + blv;
        }
        p ^= 1;
    }
}

extern "C" void kernel_launch(void* const* d_in, const int* in_sizes, int n_in,
                              void* d_out, int out_size) {
    const float* x     = (const float*)d_in[0];
    const float* w_ih  = (const float*)d_in[1];
    const float* w_hh  = (const float*)d_in[2];
    const float* b_ih  = (const float*)d_in[3];
    const float* b_hh  = (const float*)d_in[4];
    const float* w_lin = (const float*)d_in[5];
    const float* b_lin = (const float*)d_in[6];
    float* out = (float*)d_out;

    const int smem_bytes = 2 * ESTR;   // 27904
    cudaFuncSetAttribute(gru_mma_kernel, cudaFuncAttributeMaxDynamicSharedMemorySize,
                         smem_bytes);
    gru_mma_kernel<<<128, NTH, smem_bytes>>>(x, w_ih, w_hh, b_ih, b_hh,
                                             w_lin, b_lin, out);
}

// round 14
// speedup vs baseline: 3.7158x; 1.1110x over previous
#include <cuda_runtime.h>
#include <cuda_bf16.h>
#include <cstdint>

// GRU_39170101739852: B=4096, T=512, H=64 GRU + Linear(H->1), fp32.
// R13 (resubmit after infra failure): R12 with B-fragment ldmatrix offset
// fixed (k32 block at +64B, was +32B). 4 engines x 8 batches per 512-thread
// CTA (16 warps/SM). Whi register-resident; Wlo in smem via ldmatrix.x4;
// B h-fragments via ldmatrix.x4. In-register epilogue (R11 scheme).

#define TT 512
#define HH 64
#define NTH 512
#define PITCH 144        // bytes per row (72 bf16) in h tiles and Wlo
#define O_WLO 0
#define WLO_SZ 27648     // 192 rows x 144 B
#define EB0   27648
#define ESTR  6976       // per-engine: h 2x2304 | xt 2112 | red 256
#define SMEMB (EB0 + 4 * ESTR)

__device__ __forceinline__ float ftanh(float v) {
    float r; asm("tanh.approx.f32 %0, %1;" : "=f"(r) : "f"(v)); return r;
}
__device__ __forceinline__ float fsig(float v) {
    return fmaf(0.5f, ftanh(0.5f * v), 0.5f);
}
__device__ __forceinline__ uint32_t pkbf(float a, float b) {
    const __nv_bfloat16 x = __float2bfloat16(a);
    const __nv_bfloat16 y = __float2bfloat16(b);
    return (uint32_t)*(const uint16_t*)&x | ((uint32_t)*(const uint16_t*)&y << 16);
}
__device__ __forceinline__ uint32_t s2u(const void* p) {
    uint32_t a;
    asm("{ .reg .u64 t; cvta.to.shared.u64 t, %1; cvt.u32.u64 %0, t; }"
        : "=r"(a) : "l"(p));
    return a;
}

#define MMA(d, a, bb) \
    asm volatile("mma.sync.aligned.m16n8k16.row.col.f32.bf16.bf16.f32 " \
        "{%0,%1,%2,%3}, {%4,%5,%6,%7}, {%8,%9}, {%0,%1,%2,%3};" \
        : "+f"((d)[0]), "+f"((d)[1]), "+f"((d)[2]), "+f"((d)[3]) \
        : "r"((a)[0]), "r"((a)[1]), "r"((a)[2]), "r"((a)[3]), \
          "r"((bb)[0]), "r"((bb)[1]))

#define LDM4(r, addr) \
    asm volatile("ldmatrix.sync.aligned.m8n8.x4.shared.b16 {%0,%1,%2,%3}, [%4];" \
        : "=r"((r)[0]), "=r"((r)[1]), "=r"((r)[2]), "=r"((r)[3]) : "r"(addr))

__global__ void __launch_bounds__(NTH, 1)
gru_mma_kernel(const float* __restrict__ x,
               const float* __restrict__ w_ih,
               const float* __restrict__ w_hh,
               const float* __restrict__ b_ih,
               const float* __restrict__ b_hh,
               const float* __restrict__ w_lin,
               const float* __restrict__ b_lin,
               float* __restrict__ out)
{
    extern __shared__ char smem[];
    const int tid  = threadIdx.x;
    const int eng  = tid >> 7;          // engine 0..3, 8 batches each
    const int wt   = tid & 127;
    const int w    = (tid >> 5) & 3;    // warp in engine: units 16w..16w+15
    const int lane = tid & 31;
    const int g    = lane >> 2;
    const int tig  = lane & 3;
    const int bgw  = blockIdx.x * 32 + eng * 8;
    const int barid = eng + 1;

    char*  E   = smem + EB0 + eng * ESTR;
    float* xt  = (float*)(E + 4608);
    float* red = (float*)(E + 6720);

    // ---- fill Wlo tile in smem: [192 rows][pitch 144B] bf16 ----
    for (int i = tid; i < 192 * HH; i += NTH) {
        const int row = i >> 6, k = i & 63;
        const float f = w_hh[row * HH + k];
        const __nv_bfloat16 hi = __float2bfloat16(f);
        *(__nv_bfloat16*)(smem + O_WLO + row * PITCH + k * 2) =
            __float2bfloat16(f - __bfloat162float(hi));
    }
    // zero this engine's h buffers (4608 B = 1152 words)
    for (int i = wt; i < 1152; i += 128) ((uint32_t*)E)[i] = 0u;
    // x chunk 0: 8 rows x 32 t = 64 float4
    if (wt < 64) {
        const int bl = wt >> 3, q = wt & 7;
        const float4 v = *(const float4*)&x[(size_t)(bgw + bl) * TT + q * 4];
        float* xp = xt + bl * 33 + q * 4;
        xp[0] = v.x; xp[1] = v.y; xp[2] = v.z; xp[3] = v.w;
    }

    // ---- Whi fragments (registers) + bias ----
    const int uA = 16 * w + g, uB = uA + 8;
    uint32_t ahi[3][4][4];
    float biasA[3], biasB[3];
    #pragma unroll
    for (int mt = 0; mt < 3; ++mt) {
        const int rA = mt * 64 + uA, rB = mt * 64 + uB;
        biasA[mt] = (mt < 2) ? (b_ih[rA] + b_hh[rA]) : b_hh[rA];
        biasB[mt] = (mt < 2) ? (b_ih[rB] + b_hh[rB]) : b_hh[rB];
        #pragma unroll
        for (int ks = 0; ks < 4; ++ks)
            #pragma unroll
            for (int pos = 0; pos < 4; ++pos) {
                const int row = (pos & 1) ? rB : rA;
                const int col = 16 * ks + 2 * tig + ((pos >> 1) * 8);
                ahi[mt][ks][pos] = pkbf(w_hh[row * HH + col],
                                        w_hh[row * HH + col + 1]);
            }
    }

    // ldmatrix base addresses (u32 shared)
    const uint32_t sbase = s2u(smem);
    // A-lo: lane row/col inside a 16x16 tile
    const uint32_t aRow = 16 * w + (lane & 7) + 8 * ((lane >> 3) & 1);
    const uint32_t aloB = sbase + O_WLO + aRow * PITCH + (lane >> 4) * 16;
    // B: lane -> batch row (l&7), k-block (l>>3): byte cols 0,16,32,48 = k 0..31
    const uint32_t hB   = sbase + (uint32_t)(EB0 + eng * ESTR)
                        + (lane & 7) * PITCH + (lane >> 3) * 16;

    float wir[2], wiz[2], win[2], binv[2], wl[2];
    #pragma unroll
    for (int e = 0; e < 2; ++e) {
        const int u = e ? uB : uA;
        wir[e]  = w_ih[u];
        wiz[e]  = w_ih[HH + u];
        win[e]  = w_ih[2 * HH + u];
        binv[e] = b_ih[2 * HH + u];
        wl[e]   = w_lin[u];
    }
    const float blv = b_lin[0];

    float hp[2][2];   // [e][jj]
    hp[0][0] = hp[0][1] = hp[1][0] = hp[1][1] = 0.0f;

    __syncthreads();

    int p = 0;
    #pragma unroll 1
    for (int t = 0; t < TT; ++t) {
        const uint32_t hrd = hB + p * 2304;          // read buffer
        char* hwt = E + (p ^ 1) * 2304;              // write buffer

        // ---- B fragments: hi (2x ldmatrix.x4), lo (2x) ----
        // first x4 covers k[0,32); second starts at k=32 -> +64 BYTES
        uint32_t bh[8], bl2[8];
        LDM4(bh,      hrd);              // k 0..31
        LDM4(bh + 4,  hrd + 64);         // k 32..63   (FIX: was +32)
        LDM4(bl2,     hrd + 1152);
        LDM4(bl2 + 4, hrd + 1152 + 64);  // (FIX: was +32)

        // ---- acc = bias; 3-term MMA (A-lo streamed via ldmatrix) ----
        float acc[3][4];
        #pragma unroll
        for (int mt = 0; mt < 3; ++mt) {
            acc[mt][0] = biasA[mt]; acc[mt][1] = biasA[mt];
            acc[mt][2] = biasB[mt]; acc[mt][3] = biasB[mt];
        }
        #pragma unroll
        for (int mt = 0; mt < 3; ++mt) {
            #pragma unroll
            for (int ks = 0; ks < 4; ++ks) {
                MMA(acc[mt], ahi[mt][ks], (bh + 2 * ks));
                MMA(acc[mt], ahi[mt][ks], (bl2 + 2 * ks));
                uint32_t alo[4];
                LDM4(alo, aloB + mt * (64 * PITCH) + ks * 32);
                MMA(acc[mt], alo, (bh + 2 * ks));
            }
        }

        // ---- in-register epilogue: cells (e, jj), batch = 2*tig + jj ----
        const float* xb = xt + ((t >> 5) & 1) * 264;
        const int ttl = t & 31;
        float s[2];
        #pragma unroll
        for (int jj = 0; jj < 2; ++jj) {
            const int b  = 2 * tig + jj;
            const float xv = xb[b * 33 + ttl];
            float sv = 0.0f;
            #pragma unroll
            for (int e = 0; e < 2; ++e) {
                const float ga = acc[0][2 * e + jj];
                const float gz = acc[1][2 * e + jj];
                const float gn = acc[2][2 * e + jj];
                const float r  = fsig(fmaf(wir[e], xv, ga));
                const float z  = fsig(fmaf(wiz[e], xv, gz));
                const float n  = ftanh(fmaf(r, gn, fmaf(win[e], xv, binv[e])));
                const float h  = fmaf(z, hp[e][jj] - n, n);
                hp[e][jj] = h;
                sv = fmaf(wl[e], h, sv);
                const int u = e ? uB : uA;
                const __nv_bfloat16 hb = __float2bfloat16(h);
                *(__nv_bfloat16*)(hwt + b * PITCH + u * 2) = hb;
                *(__nv_bfloat16*)(hwt + 1152 + b * PITCH + u * 2) =
                    __float2bfloat16(h - __bfloat162float(hb));
            }
            s[jj] = sv;
        }

        // ---- output partials: reduce over g ----
        #pragma unroll
        for (int off = 4; off <= 16; off <<= 1) {
            s[0] += __shfl_xor_sync(0xffffffffu, s[0], off);
            s[1] += __shfl_xor_sync(0xffffffffu, s[1], off);
        }
        float* rcur = red + (t & 1) * 32;
        if (g == 0) {
            rcur[(2 * tig + 0) * 4 + w] = s[0];
            rcur[(2 * tig + 1) * 4 + w] = s[1];
        }

        // ---- stage next x chunk ----
        if (((t + 1) & 31) == 0 && (t + 1) < TT && wt < 64) {
            const int bl = wt >> 3, q = wt & 7;
            const float4 v = *(const float4*)&x[(size_t)(bgw + bl) * TT + (t + 1) + q * 4];
            float* xp = xt + (((t + 1) >> 5) & 1) * 264 + bl * 33 + q * 4;
            xp[0] = v.x; xp[1] = v.y; xp[2] = v.z; xp[3] = v.w;
        }

        asm volatile("bar.sync %0, 128;" :: "r"(barid) : "memory");

        if (wt < 8) {
            const float4 r4 = *(const float4*)&rcur[wt * 4];
            out[(size_t)(bgw + wt) * TT + t] = (r4.x + r4.y) + (r4.z + r4.w) + blv;
        }
        p ^= 1;
    }
}

extern "C" void kernel_launch(void* const* d_in, const int* in_sizes, int n_in,
                              void* d_out, int out_size) {
    const float* x     = (const float*)d_in[0];
    const float* w_ih  = (const float*)d_in[1];
    const float* w_hh  = (const float*)d_in[2];
    const float* b_ih  = (const float*)d_in[3];
    const float* b_hh  = (const float*)d_in[4];
    const float* w_lin = (const float*)d_in[5];
    const float* b_lin = (const float*)d_in[6];
    float* out = (float*)d_out;

    cudaFuncSetAttribute(gru_mma_kernel, cudaFuncAttributeMaxDynamicSharedMemorySize,
                         SMEMB);
    gru_mma_kernel<<<128, NTH, SMEMB>>>(x, w_ih, w_hh, b_ih, b_hh,
                                        w_lin, b_lin, out);
}